// round 2
// baseline (speedup 1.0000x reference)
#include <cuda_runtime.h>

// Problem constants
#define HW4    65536          // (512*512)/4 float4-groups per (b,c) plane
#define NGROUP 524288         // NPIX/4
#define NPIX   2097152
#define GRID   1024
#define TPB    256
// GRID*TPB = 262144 threads, 2 groups each

__device__ float        g_psum[GRID];
__device__ float        g_pmax[GRID];
__device__ unsigned int g_count = 0;

__global__ __launch_bounds__(TPB) void map_loss_fused(
    const float4* __restrict__ tg,
    const float4* __restrict__ mu,
    const float4* __restrict__ sy,
    float* __restrict__ out)
{
    float lsum = 0.0f;
    float lmax = -3.0e38f;

    const unsigned t = blockIdx.x * TPB + threadIdx.x;

    #pragma unroll
    for (int it = 0; it < 2; ++it) {
        const unsigned g  = t + (unsigned)it * (GRID * TPB);   // group of 4 pixels
        const unsigned b  = g >> 16;                            // batch index
        const unsigned p  = g & (HW4 - 1);                      // float4 index in plane
        const unsigned tb = b * 3 * HW4 + p;

        // Residuals for 4 pixels, 3 channels (all float4, coalesced)
        const float4 T0 = tg[tb],           M0 = mu[tb];
        const float4 T1 = tg[tb + HW4],     M1 = mu[tb + HW4];
        const float4 T2 = tg[tb + 2 * HW4], M2 = mu[tb + 2 * HW4];
        const float r0[4] = {T0.x - M0.x, T0.y - M0.y, T0.z - M0.z, T0.w - M0.w};
        const float r1[4] = {T1.x - M1.x, T1.y - M1.y, T1.z - M1.z, T1.w - M1.w};
        const float r2[4] = {T2.x - M2.x, T2.y - M2.y, T2.z - M2.z, T2.w - M2.w};

        // sigma_y for 4 pixels: 36 contiguous floats = 9 float4 (16B aligned)
        float S[36];
        #pragma unroll
        for (int k = 0; k < 9; ++k) {
            const float4 v = sy[(size_t)9 * g + k];
            S[4 * k + 0] = v.x; S[4 * k + 1] = v.y;
            S[4 * k + 2] = v.z; S[4 * k + 3] = v.w;
        }

        float quad[4], det[4];
        #pragma unroll
        for (int j = 0; j < 4; ++j) {
            const float a  = S[9 * j + 0];
            const float bb = S[9 * j + 1];
            const float c  = S[9 * j + 2];
            const float d  = S[9 * j + 4];
            const float e  = S[9 * j + 5];
            const float f  = S[9 * j + 8];
            const float A00 = d * f - e * e;
            const float A01 = c * e - bb * f;
            const float A02 = bb * e - c * d;
            const float A11 = a * f - c * c;
            const float A12 = bb * c - a * e;
            const float A22 = a * d - bb * bb;
            det[j] = a * A00 + bb * A01 + c * A02;
            quad[j] = r0[j] * r0[j] * A00 + r1[j] * r1[j] * A11 + r2[j] * r2[j] * A22
                    + 2.0f * (r0[j] * r1[j] * A01 + r0[j] * r2[j] * A02 + r1[j] * r2[j] * A12);
            // guard: t1 = 0.5*quad/det > 1e8  <=>  quad - 2e8*det > 0   (det > 0)
            lmax = fmaxf(lmax, quad[j] - 2.0e8f * det[j]);
        }

        // Combine 4 pixels: one division + one log per group
        const float d01 = det[0] * det[1];
        const float d23 = det[2] * det[3];
        const float num = (quad[0] * det[1] + quad[1] * det[0]) * d23
                        + (quad[2] * det[3] + quad[3] * det[2]) * d01;
        const float dp  = d01 * d23;                 // >= 1, <= ~1e13 : safe
        lsum += 0.5f * (__fdividef(num, dp) + __logf(dp));
    }

    // ---- intra-block reduction ----
    const int lane = threadIdx.x & 31;
    const int wid  = threadIdx.x >> 5;
    #pragma unroll
    for (int off = 16; off > 0; off >>= 1) {
        lsum += __shfl_down_sync(0xffffffffu, lsum, off);
        lmax  = fmaxf(lmax, __shfl_down_sync(0xffffffffu, lmax, off));
    }
    __shared__ float wsum[TPB / 32];
    __shared__ float wmax[TPB / 32];
    if (lane == 0) { wsum[wid] = lsum; wmax[wid] = lmax; }
    __syncthreads();
    __shared__ bool s_last;
    if (threadIdx.x == 0) {
        float bs = wsum[0], bm = wmax[0];
        #pragma unroll
        for (int w = 1; w < TPB / 32; ++w) { bs += wsum[w]; bm = fmaxf(bm, wmax[w]); }
        g_psum[blockIdx.x] = bs;
        g_pmax[blockIdx.x] = bm;
        __threadfence();
        const unsigned done = atomicAdd(&g_count, 1u);
        s_last = (done == GRID - 1);
    }
    __syncthreads();

    // ---- last block finalizes (no second launch) ----
    if (s_last) {
        double ds = 0.0;
        float  dm = -3.0e38f;
        #pragma unroll
        for (int k = 0; k < GRID / TPB; ++k) {
            const int idx = threadIdx.x + k * TPB;
            ds += (double)g_psum[idx];
            dm  = fmaxf(dm, g_pmax[idx]);
        }
        __shared__ double fsum[TPB];
        __shared__ float  fmaxv[TPB];
        fsum[threadIdx.x]  = ds;
        fmaxv[threadIdx.x] = dm;
        __syncthreads();
        #pragma unroll
        for (int off = TPB / 2; off > 0; off >>= 1) {
            if (threadIdx.x < off) {
                fsum[threadIdx.x] += fsum[threadIdx.x + off];
                fmaxv[threadIdx.x] = fmaxf(fmaxv[threadIdx.x], fmaxv[threadIdx.x + off]);
            }
            __syncthreads();
        }
        if (threadIdx.x == 0) {
            float loss = (float)(fsum[0] / (double)NPIX);
            if (fmaxv[0] > 0.0f) loss = 0.0f;   // max(t1) > 1e8 guard
            out[0] = loss;
            g_count = 0;                         // reset for next graph replay
        }
    }
}

extern "C" void kernel_launch(void* const* d_in, const int* in_sizes, int n_in,
                              void* d_out, int out_size)
{
    // metadata order: target, mu, sigma_mu, sigma_n, sigma_y
    const float4* target = (const float4*)d_in[0];
    const float4* mu     = (const float4*)d_in[1];
    const float4* sy     = (const float4*)d_in[4];
    float* out = (float*)d_out;

    map_loss_fused<<<GRID, TPB>>>(target, mu, sy, out);
}

// round 3
// speedup vs baseline: 1.0922x; 1.0922x over previous
#include <cuda_runtime.h>

// Problem constants
#define HW4    65536          // (512*512)/4 float4-groups per (b,c) plane
#define NGROUP 524288         // NPIX/4
#define NPIX   2097152
#define GRID   2048
#define TPB    256
// GRID*TPB = 524288 threads = exactly one 4-pixel group per thread

__device__ float        g_psum[GRID];
__device__ float        g_pmax[GRID];
__device__ unsigned int g_count = 0;

__global__ __launch_bounds__(TPB) void map_loss_fused(
    const float4* __restrict__ tg,
    const float4* __restrict__ mu,
    const float4* __restrict__ sy,
    float* __restrict__ out)
{
    const unsigned g  = blockIdx.x * TPB + threadIdx.x;   // group of 4 pixels
    const unsigned b  = g >> 16;                          // batch index
    const unsigned p  = g & (HW4 - 1);                    // float4 index in plane
    const unsigned tb = b * 3 * HW4 + p;

    // ---- front-batch ALL loads (15 independent LDG.128) ----
    float4 S0 = sy[(size_t)9 * g + 0];
    float4 S1 = sy[(size_t)9 * g + 1];
    float4 S2 = sy[(size_t)9 * g + 2];
    float4 S3 = sy[(size_t)9 * g + 3];
    float4 S4 = sy[(size_t)9 * g + 4];
    float4 S5 = sy[(size_t)9 * g + 5];
    float4 S6 = sy[(size_t)9 * g + 6];
    float4 S7 = sy[(size_t)9 * g + 7];
    float4 S8 = sy[(size_t)9 * g + 8];
    const float4 T0 = tg[tb],           M0 = mu[tb];
    const float4 T1 = tg[tb + HW4],     M1 = mu[tb + HW4];
    const float4 T2 = tg[tb + 2 * HW4], M2 = mu[tb + 2 * HW4];

    const float r0[4] = {T0.x - M0.x, T0.y - M0.y, T0.z - M0.z, T0.w - M0.w};
    const float r1[4] = {T1.x - M1.x, T1.y - M1.y, T1.z - M1.z, T1.w - M1.w};
    const float r2[4] = {T2.x - M2.x, T2.y - M2.y, T2.z - M2.z, T2.w - M2.w};

    float S[36];
    S[0]=S0.x; S[1]=S0.y; S[2]=S0.z; S[3]=S0.w;
    S[4]=S1.x; S[5]=S1.y; S[6]=S1.z; S[7]=S1.w;
    S[8]=S2.x; S[9]=S2.y; S[10]=S2.z; S[11]=S2.w;
    S[12]=S3.x; S[13]=S3.y; S[14]=S3.z; S[15]=S3.w;
    S[16]=S4.x; S[17]=S4.y; S[18]=S4.z; S[19]=S4.w;
    S[20]=S5.x; S[21]=S5.y; S[22]=S5.z; S[23]=S5.w;
    S[24]=S6.x; S[25]=S6.y; S[26]=S6.z; S[27]=S6.w;
    S[28]=S7.x; S[29]=S7.y; S[30]=S7.z; S[31]=S7.w;
    S[32]=S8.x; S[33]=S8.y; S[34]=S8.z; S[35]=S8.w;

    float lmax = -3.0e38f;
    float quad[4], det[4];
    #pragma unroll
    for (int j = 0; j < 4; ++j) {
        const float a  = S[9 * j + 0];
        const float bb = S[9 * j + 1];
        const float c  = S[9 * j + 2];
        const float d  = S[9 * j + 4];
        const float e  = S[9 * j + 5];
        const float f  = S[9 * j + 8];
        const float A00 = d * f - e * e;
        const float A01 = c * e - bb * f;
        const float A02 = bb * e - c * d;
        const float A11 = a * f - c * c;
        const float A12 = bb * c - a * e;
        const float A22 = a * d - bb * bb;
        det[j] = a * A00 + bb * A01 + c * A02;
        quad[j] = r0[j] * r0[j] * A00 + r1[j] * r1[j] * A11 + r2[j] * r2[j] * A22
                + 2.0f * (r0[j] * r1[j] * A01 + r0[j] * r2[j] * A02 + r1[j] * r2[j] * A12);
        // guard: t1 = 0.5*quad/det > 1e8  <=>  quad - 2e8*det > 0   (det > 0)
        lmax = fmaxf(lmax, quad[j] - 2.0e8f * det[j]);
    }

    // Combine 4 pixels: one division + one log per group
    const float d01 = det[0] * det[1];
    const float d23 = det[2] * det[3];
    const float num = (quad[0] * det[1] + quad[1] * det[0]) * d23
                    + (quad[2] * det[3] + quad[3] * det[2]) * d01;
    const float dp  = d01 * d23;                 // dets >= 1, product <= ~1e13 : safe
    float lsum = 0.5f * (__fdividef(num, dp) + __logf(dp));

    // ---- intra-block reduction ----
    const int lane = threadIdx.x & 31;
    const int wid  = threadIdx.x >> 5;
    #pragma unroll
    for (int off = 16; off > 0; off >>= 1) {
        lsum += __shfl_down_sync(0xffffffffu, lsum, off);
        lmax  = fmaxf(lmax, __shfl_down_sync(0xffffffffu, lmax, off));
    }
    __shared__ float wsum[TPB / 32];
    __shared__ float wmax[TPB / 32];
    if (lane == 0) { wsum[wid] = lsum; wmax[wid] = lmax; }
    __syncthreads();
    __shared__ bool s_last;
    if (threadIdx.x == 0) {
        float bs = wsum[0], bm = wmax[0];
        #pragma unroll
        for (int w = 1; w < TPB / 32; ++w) { bs += wsum[w]; bm = fmaxf(bm, wmax[w]); }
        g_psum[blockIdx.x] = bs;
        g_pmax[blockIdx.x] = bm;
        __threadfence();
        const unsigned done = atomicAdd(&g_count, 1u);
        s_last = (done == GRID - 1);
    }
    __syncthreads();

    // ---- last block finalizes (no second launch) ----
    if (s_last) {
        double ds = 0.0;
        float  dm = -3.0e38f;
        #pragma unroll
        for (int k = 0; k < GRID / TPB; ++k) {
            const int idx = threadIdx.x + k * TPB;
            ds += (double)g_psum[idx];
            dm  = fmaxf(dm, g_pmax[idx]);
        }
        __shared__ double fsum[TPB];
        __shared__ float  fmaxv[TPB];
        fsum[threadIdx.x]  = ds;
        fmaxv[threadIdx.x] = dm;
        __syncthreads();
        #pragma unroll
        for (int off = TPB / 2; off > 0; off >>= 1) {
            if (threadIdx.x < off) {
                fsum[threadIdx.x] += fsum[threadIdx.x + off];
                fmaxv[threadIdx.x] = fmaxf(fmaxv[threadIdx.x], fmaxv[threadIdx.x + off]);
            }
            __syncthreads();
        }
        if (threadIdx.x == 0) {
            float loss = (float)(fsum[0] / (double)NPIX);
            if (fmaxv[0] > 0.0f) loss = 0.0f;   // max(t1) > 1e8 guard
            out[0] = loss;
            g_count = 0;                         // reset for next graph replay
        }
    }
}

extern "C" void kernel_launch(void* const* d_in, const int* in_sizes, int n_in,
                              void* d_out, int out_size)
{
    // metadata order: target, mu, sigma_mu, sigma_n, sigma_y
    const float4* target = (const float4*)d_in[0];
    const float4* mu     = (const float4*)d_in[1];
    const float4* sy     = (const float4*)d_in[4];
    float* out = (float*)d_out;

    map_loss_fused<<<GRID, TPB>>>(target, mu, sy, out);
}

// round 4
// speedup vs baseline: 1.1689x; 1.0702x over previous
#include <cuda_runtime.h>
#include <cstdint>

// Problem constants
#define HW4    65536          // (512*512)/4 float4-groups per (b,c) plane
#define NGROUP 524288         // NPIX/4
#define NPIX   2097152
#define TPB    128
#define GPB    128            // groups per block (== TPB, 1 group/thread)
#define GRID   4096           // NGROUP / GPB

#define SY_TILE_BYTES (GPB * 36 * 4)   // 18432 B of sigma_y per block

__device__ float        g_psum[GRID];
__device__ float        g_pmax[GRID];
__device__ unsigned int g_count = 0;

__device__ __forceinline__ uint32_t smem_u32(const void* p) {
    uint32_t a;
    asm("{ .reg .u64 t; cvta.to.shared.u64 t, %1; cvt.u32.u64 %0, t; }" : "=r"(a) : "l"(p));
    return a;
}

__global__ __launch_bounds__(TPB) void map_loss_fused(
    const float4* __restrict__ tg,
    const float4* __restrict__ mu,
    const float*  __restrict__ sy,
    float* __restrict__ out)
{
    __shared__ alignas(128) float4 s_sy[GPB * 9];   // 18432 B
    __shared__ alignas(8)  uint64_t s_mbar;

    const unsigned tid = threadIdx.x;
    const unsigned g   = blockIdx.x * GPB + tid;    // this thread's 4-pixel group
    const unsigned b   = g >> 16;                   // batch index
    const unsigned p   = g & (HW4 - 1);             // float4 index within plane
    const unsigned tb  = b * 3 * HW4 + p;

    const uint32_t mbar = smem_u32(&s_mbar);

    // ---- init mbarrier, then kick off the bulk sigma copy from one thread ----
    if (tid == 0) {
        asm volatile("mbarrier.init.shared.b64 [%0], 1;" :: "r"(mbar) : "memory");
    }
    __syncthreads();
    if (tid == 0) {
        asm volatile("mbarrier.arrive.expect_tx.shared.b64 _, [%0], %1;"
                     :: "r"(mbar), "r"((uint32_t)SY_TILE_BYTES) : "memory");
        const char* src = (const char*)sy + (size_t)blockIdx.x * SY_TILE_BYTES;
        asm volatile(
            "cp.async.bulk.shared::cta.global.mbarrier::complete_tx::bytes "
            "[%0], [%1], %2, [%3];"
            :: "r"(smem_u32(s_sy)), "l"(src), "r"((uint32_t)SY_TILE_BYTES), "r"(mbar)
            : "memory");
    }

    // ---- overlap: issue tg/mu loads (6 independent LDG.128) while TMA fills ----
    const float4 T0 = tg[tb],           M0 = mu[tb];
    const float4 T1 = tg[tb + HW4],     M1 = mu[tb + HW4];
    const float4 T2 = tg[tb + 2 * HW4], M2 = mu[tb + 2 * HW4];
    const float r0[4] = {T0.x - M0.x, T0.y - M0.y, T0.z - M0.z, T0.w - M0.w};
    const float r1[4] = {T1.x - M1.x, T1.y - M1.y, T1.z - M1.z, T1.w - M1.w};
    const float r2[4] = {T2.x - M2.x, T2.y - M2.y, T2.z - M2.z, T2.w - M2.w};

    // ---- wait for sigma tile ----
    {
        uint32_t done;
        asm volatile(
            "{\n\t.reg .pred p;\n\t"
            "mbarrier.try_wait.parity.acquire.cta.shared::cta.b64 p, [%1], 0;\n\t"
            "selp.b32 %0, 1, 0, p;\n\t}"
            : "=r"(done) : "r"(mbar) : "memory");
        while (!done) {
            asm volatile(
                "{\n\t.reg .pred p;\n\t"
                "mbarrier.try_wait.parity.acquire.cta.shared::cta.b64 p, [%1], 0, 0x989680;\n\t"
                "selp.b32 %0, 1, 0, p;\n\t}"
                : "=r"(done) : "r"(mbar) : "memory");
        }
    }

    // ---- per-group math (sigma from smem) ----
    float S[36];
    #pragma unroll
    for (int k = 0; k < 9; ++k) {
        const float4 v = s_sy[tid * 9 + k];
        S[4 * k + 0] = v.x; S[4 * k + 1] = v.y;
        S[4 * k + 2] = v.z; S[4 * k + 3] = v.w;
    }

    float lmax = -3.0e38f;
    float quad[4], det[4];
    #pragma unroll
    for (int j = 0; j < 4; ++j) {
        const float a  = S[9 * j + 0];
        const float bb = S[9 * j + 1];
        const float c  = S[9 * j + 2];
        const float d  = S[9 * j + 4];
        const float e  = S[9 * j + 5];
        const float f  = S[9 * j + 8];
        const float A00 = d * f - e * e;
        const float A01 = c * e - bb * f;
        const float A02 = bb * e - c * d;
        const float A11 = a * f - c * c;
        const float A12 = bb * c - a * e;
        const float A22 = a * d - bb * bb;
        det[j] = a * A00 + bb * A01 + c * A02;
        quad[j] = r0[j] * r0[j] * A00 + r1[j] * r1[j] * A11 + r2[j] * r2[j] * A22
                + 2.0f * (r0[j] * r1[j] * A01 + r0[j] * r2[j] * A02 + r1[j] * r2[j] * A12);
        // guard: t1 = 0.5*quad/det > 1e8  <=>  quad - 2e8*det > 0   (det > 0)
        lmax = fmaxf(lmax, quad[j] - 2.0e8f * det[j]);
    }

    // one division + one log per 4 pixels
    const float d01 = det[0] * det[1];
    const float d23 = det[2] * det[3];
    const float num = (quad[0] * det[1] + quad[1] * det[0]) * d23
                    + (quad[2] * det[3] + quad[3] * det[2]) * d01;
    const float dp  = d01 * d23;                 // dets >= 1, product <= ~1e13 : safe
    float lsum = 0.5f * (__fdividef(num, dp) + __logf(dp));

    // ---- intra-block reduction (4 warps) ----
    const int lane = tid & 31;
    const int wid  = tid >> 5;
    #pragma unroll
    for (int off = 16; off > 0; off >>= 1) {
        lsum += __shfl_down_sync(0xffffffffu, lsum, off);
        lmax  = fmaxf(lmax, __shfl_down_sync(0xffffffffu, lmax, off));
    }
    __shared__ float wsum[TPB / 32];
    __shared__ float wmax[TPB / 32];
    if (lane == 0) { wsum[wid] = lsum; wmax[wid] = lmax; }
    __syncthreads();
    __shared__ bool s_last;
    if (tid == 0) {
        float bs = wsum[0], bm = wmax[0];
        #pragma unroll
        for (int w = 1; w < TPB / 32; ++w) { bs += wsum[w]; bm = fmaxf(bm, wmax[w]); }
        g_psum[blockIdx.x] = bs;
        g_pmax[blockIdx.x] = bm;
        __threadfence();
        const unsigned done = atomicAdd(&g_count, 1u);
        s_last = (done == GRID - 1);
    }
    __syncthreads();

    // ---- last block finalizes (no second launch) ----
    if (s_last) {
        double ds = 0.0;
        float  dm = -3.0e38f;
        #pragma unroll
        for (int k = 0; k < GRID / TPB; ++k) {
            const int idx = tid + k * TPB;
            ds += (double)g_psum[idx];
            dm  = fmaxf(dm, g_pmax[idx]);
        }
        __shared__ double fsum[TPB];
        __shared__ float  fmaxv[TPB];
        fsum[tid]  = ds;
        fmaxv[tid] = dm;
        __syncthreads();
        #pragma unroll
        for (int off = TPB / 2; off > 0; off >>= 1) {
            if (tid < off) {
                fsum[tid] += fsum[tid + off];
                fmaxv[tid] = fmaxf(fmaxv[tid], fmaxv[tid + off]);
            }
            __syncthreads();
        }
        if (tid == 0) {
            float loss = (float)(fsum[0] / (double)NPIX);
            if (fmaxv[0] > 0.0f) loss = 0.0f;   // max(t1) > 1e8 guard
            out[0] = loss;
            g_count = 0;                         // reset for next graph replay
        }
    }
}

extern "C" void kernel_launch(void* const* d_in, const int* in_sizes, int n_in,
                              void* d_out, int out_size)
{
    // metadata order: target, mu, sigma_mu, sigma_n, sigma_y
    const float4* target = (const float4*)d_in[0];
    const float4* mu     = (const float4*)d_in[1];
    const float*  sy     = (const float*)d_in[4];
    float* out = (float*)d_out;

    map_loss_fused<<<GRID, TPB>>>(target, mu, sy, out);
}

// round 5
// speedup vs baseline: 1.2482x; 1.0679x over previous
#include <cuda_runtime.h>
#include <cstdint>

// Problem constants
#define HW4    65536          // (512*512)/4 float4-groups per (b,c) plane
#define NGROUP 524288         // NPIX/4
#define NPIX   2097152
#define TPB    128
#define GPB    128            // groups per tile (== TPB, 1 group/thread)
#define TILES  4              // tiles per block
#define GRID   1024           // NGROUP / (GPB*TILES)

#define SY_TILE_BYTES (GPB * 36 * 4)   // 18432 B of sigma_y per tile

__device__ float        g_psum[GRID];
__device__ float        g_pmax[GRID];
__device__ unsigned int g_count = 0;

__device__ __forceinline__ uint32_t smem_u32(const void* p) {
    uint32_t a;
    asm("{ .reg .u64 t; cvta.to.shared.u64 t, %1; cvt.u32.u64 %0, t; }" : "=r"(a) : "l"(p));
    return a;
}

__device__ __forceinline__ void tma_tile(uint32_t dst, const float* sy,
                                         unsigned tile, uint32_t mbar) {
    asm volatile("mbarrier.arrive.expect_tx.shared.b64 _, [%0], %1;"
                 :: "r"(mbar), "r"((uint32_t)SY_TILE_BYTES) : "memory");
    const char* src = (const char*)sy + (size_t)tile * SY_TILE_BYTES;
    asm volatile(
        "cp.async.bulk.shared::cta.global.mbarrier::complete_tx::bytes "
        "[%0], [%1], %2, [%3];"
        :: "r"(dst), "l"(src), "r"((uint32_t)SY_TILE_BYTES), "r"(mbar)
        : "memory");
}

__device__ __forceinline__ void mbar_wait(uint32_t mbar, uint32_t parity) {
    uint32_t done;
    asm volatile(
        "{\n\t.reg .pred p;\n\t"
        "mbarrier.try_wait.parity.acquire.cta.shared::cta.b64 p, [%1], %2;\n\t"
        "selp.b32 %0, 1, 0, p;\n\t}"
        : "=r"(done) : "r"(mbar), "r"(parity) : "memory");
    while (!done) {
        asm volatile(
            "{\n\t.reg .pred p;\n\t"
            "mbarrier.try_wait.parity.acquire.cta.shared::cta.b64 p, [%1], %2, 0x989680;\n\t"
            "selp.b32 %0, 1, 0, p;\n\t}"
            : "=r"(done) : "r"(mbar), "r"(parity) : "memory");
    }
}

__global__ __launch_bounds__(TPB) void map_loss_fused(
    const float4* __restrict__ tg,
    const float4* __restrict__ mu,
    const float*  __restrict__ sy,
    float* __restrict__ out)
{
    __shared__ alignas(128) float4 s_sy[2][GPB * 9];   // 2 x 18432 B
    __shared__ alignas(8)  uint64_t s_mbar[2];

    const unsigned tid       = threadIdx.x;
    const unsigned base_tile = blockIdx.x * TILES;

    // ---- init barriers, prefetch tiles 0 and 1 ----
    if (tid == 0) {
        asm volatile("mbarrier.init.shared.b64 [%0], 1;" :: "r"(smem_u32(&s_mbar[0])) : "memory");
        asm volatile("mbarrier.init.shared.b64 [%0], 1;" :: "r"(smem_u32(&s_mbar[1])) : "memory");
    }
    __syncthreads();
    if (tid == 0) {
        tma_tile(smem_u32(s_sy[0]), sy, base_tile + 0, smem_u32(&s_mbar[0]));
        tma_tile(smem_u32(s_sy[1]), sy, base_tile + 1, smem_u32(&s_mbar[1]));
    }

    float lsum = 0.0f;
    float lmax = -3.0e38f;

    #pragma unroll
    for (int t = 0; t < TILES; ++t) {
        const int      stage  = t & 1;
        const uint32_t parity = (t >> 1) & 1;

        // group for this thread in this tile
        const unsigned g  = (base_tile + t) * GPB + tid;
        const unsigned b  = g >> 16;                 // batch index
        const unsigned p  = g & (HW4 - 1);           // float4 index within plane
        const unsigned tb = b * 3 * HW4 + p;

        // issue + consume tg/mu loads BEFORE waiting on the sigma TMA,
        // so the LDGs overlap the bulk copy in flight
        const float4 T0 = tg[tb],           M0 = mu[tb];
        const float4 T1 = tg[tb + HW4],     M1 = mu[tb + HW4];
        const float4 T2 = tg[tb + 2 * HW4], M2 = mu[tb + 2 * HW4];
        const float r0[4] = {T0.x - M0.x, T0.y - M0.y, T0.z - M0.z, T0.w - M0.w};
        const float r1[4] = {T1.x - M1.x, T1.y - M1.y, T1.z - M1.z, T1.w - M1.w};
        const float r2[4] = {T2.x - M2.x, T2.y - M2.y, T2.z - M2.z, T2.w - M2.w};

        mbar_wait(smem_u32(&s_mbar[stage]), parity);

        // sigma for 4 pixels from smem
        float S[36];
        #pragma unroll
        for (int k = 0; k < 9; ++k) {
            const float4 v = s_sy[stage][tid * 9 + k];
            S[4 * k + 0] = v.x; S[4 * k + 1] = v.y;
            S[4 * k + 2] = v.z; S[4 * k + 3] = v.w;
        }

        float quad[4], det[4];
        #pragma unroll
        for (int j = 0; j < 4; ++j) {
            const float a  = S[9 * j + 0];
            const float bb = S[9 * j + 1];
            const float c  = S[9 * j + 2];
            const float d  = S[9 * j + 4];
            const float e  = S[9 * j + 5];
            const float f  = S[9 * j + 8];
            const float A00 = d * f - e * e;
            const float A01 = c * e - bb * f;
            const float A02 = bb * e - c * d;
            const float A11 = a * f - c * c;
            const float A12 = bb * c - a * e;
            const float A22 = a * d - bb * bb;
            det[j] = a * A00 + bb * A01 + c * A02;
            quad[j] = r0[j] * r0[j] * A00 + r1[j] * r1[j] * A11 + r2[j] * r2[j] * A22
                    + 2.0f * (r0[j] * r1[j] * A01 + r0[j] * r2[j] * A02 + r1[j] * r2[j] * A12);
            // guard: t1 = 0.5*quad/det > 1e8  <=>  quad - 2e8*det > 0  (det > 0)
            lmax = fmaxf(lmax, quad[j] - 2.0e8f * det[j]);
        }

        // one division + one log per 4 pixels
        const float d01 = det[0] * det[1];
        const float d23 = det[2] * det[3];
        const float num = (quad[0] * det[1] + quad[1] * det[0]) * d23
                        + (quad[2] * det[3] + quad[3] * det[2]) * d01;
        const float dp  = d01 * d23;            // dets >= 1, product <= ~1e13 : safe
        lsum += 0.5f * (__fdividef(num, dp) + __logf(dp));

        // stage buffer free -> refill with tile t+2
        if (t + 2 < TILES) {
            __syncthreads();
            if (tid == 0)
                tma_tile(smem_u32(s_sy[stage]), sy, base_tile + t + 2,
                         smem_u32(&s_mbar[stage]));
        }
    }

    // ---- intra-block reduction (4 warps) ----
    const int lane = tid & 31;
    const int wid  = tid >> 5;
    #pragma unroll
    for (int off = 16; off > 0; off >>= 1) {
        lsum += __shfl_down_sync(0xffffffffu, lsum, off);
        lmax  = fmaxf(lmax, __shfl_down_sync(0xffffffffu, lmax, off));
    }
    __shared__ float wsum[TPB / 32];
    __shared__ float wmax[TPB / 32];
    if (lane == 0) { wsum[wid] = lsum; wmax[wid] = lmax; }
    __syncthreads();
    __shared__ bool s_last;
    if (tid == 0) {
        float bs = wsum[0], bm = wmax[0];
        #pragma unroll
        for (int w = 1; w < TPB / 32; ++w) { bs += wsum[w]; bm = fmaxf(bm, wmax[w]); }
        g_psum[blockIdx.x] = bs;
        g_pmax[blockIdx.x] = bm;
        __threadfence();
        const unsigned done = atomicAdd(&g_count, 1u);
        s_last = (done == GRID - 1);
    }
    __syncthreads();

    // ---- last block finalizes (no second launch) ----
    if (s_last) {
        double ds = 0.0;
        float  dm = -3.0e38f;
        #pragma unroll
        for (int k = 0; k < GRID / TPB; ++k) {
            const int idx = tid + k * TPB;
            ds += (double)g_psum[idx];
            dm  = fmaxf(dm, g_pmax[idx]);
        }
        __shared__ double fsum[TPB];
        __shared__ float  fmaxv[TPB];
        fsum[tid]  = ds;
        fmaxv[tid] = dm;
        __syncthreads();
        #pragma unroll
        for (int off = TPB / 2; off > 0; off >>= 1) {
            if (tid < off) {
                fsum[tid] += fsum[tid + off];
                fmaxv[tid] = fmaxf(fmaxv[tid], fmaxv[tid + off]);
            }
            __syncthreads();
        }
        if (tid == 0) {
            float loss = (float)(fsum[0] / (double)NPIX);
            if (fmaxv[0] > 0.0f) loss = 0.0f;   // max(t1) > 1e8 guard
            out[0] = loss;
            g_count = 0;                         // reset for next graph replay
        }
    }
}

extern "C" void kernel_launch(void* const* d_in, const int* in_sizes, int n_in,
                              void* d_out, int out_size)
{
    // metadata order: target, mu, sigma_mu, sigma_n, sigma_y
    const float4* target = (const float4*)d_in[0];
    const float4* mu     = (const float4*)d_in[1];
    const float*  sy     = (const float*)d_in[4];
    float* out = (float*)d_out;

    map_loss_fused<<<GRID, TPB>>>(target, mu, sy, out);
}

// round 6
// speedup vs baseline: 1.2571x; 1.0071x over previous
#include <cuda_runtime.h>
#include <cstdint>

// Problem constants
#define HW4    65536          // (512*512)/4 float4-groups per (b,c) plane
#define NGROUP 524288         // NPIX/4
#define NPIX   2097152
#define TPB    128
#define GPB    128            // groups per tile (== TPB, 1 group/thread)
#define TILES  4              // tiles per block
#define GRID   1024           // NGROUP / (GPB*TILES)

#define SY_TILE_BYTES  (GPB * 36 * 4)     // 18432 B sigma_y per tile
#define CH_TILE_BYTES  (GPB * 16)         // 2048 B per channel segment
#define TILE_TX_BYTES  (SY_TILE_BYTES + 6 * CH_TILE_BYTES)   // 30720 B

__device__ float        g_psum[GRID];
__device__ float        g_pmax[GRID];
__device__ unsigned int g_count = 0;

__device__ __forceinline__ uint32_t smem_u32(const void* p) {
    uint32_t a;
    asm("{ .reg .u64 t; cvta.to.shared.u64 t, %1; cvt.u32.u64 %0, t; }" : "=r"(a) : "l"(p));
    return a;
}

__device__ __forceinline__ void bulk_cp(uint32_t dst, const void* src,
                                        uint32_t bytes, uint32_t mbar) {
    asm volatile(
        "cp.async.bulk.shared::cta.global.mbarrier::complete_tx::bytes "
        "[%0], [%1], %2, [%3];"
        :: "r"(dst), "l"(src), "r"(bytes), "r"(mbar) : "memory");
}

__device__ __forceinline__ void mbar_wait(uint32_t mbar, uint32_t parity) {
    uint32_t done;
    asm volatile(
        "{\n\t.reg .pred p;\n\t"
        "mbarrier.try_wait.parity.acquire.cta.shared::cta.b64 p, [%1], %2;\n\t"
        "selp.b32 %0, 1, 0, p;\n\t}"
        : "=r"(done) : "r"(mbar), "r"(parity) : "memory");
    while (!done) {
        asm volatile(
            "{\n\t.reg .pred p;\n\t"
            "mbarrier.try_wait.parity.acquire.cta.shared::cta.b64 p, [%1], %2, 0x989680;\n\t"
            "selp.b32 %0, 1, 0, p;\n\t}"
            : "=r"(done) : "r"(mbar), "r"(parity) : "memory");
    }
}

struct SmemStage {
    float4 sy[GPB * 9];     // 18432 B
    float4 t[3][GPB];       //  6144 B
    float4 m[3][GPB];       //  6144 B
};

__device__ __forceinline__ void tma_tile(const SmemStage* st, const float* sy,
                                         const float* tg, const float* mu,
                                         unsigned tile, uint32_t mbar) {
    asm volatile("mbarrier.arrive.expect_tx.shared.b64 _, [%0], %1;"
                 :: "r"(mbar), "r"((uint32_t)TILE_TX_BYTES) : "memory");
    bulk_cp(smem_u32(st->sy), (const char*)sy + (size_t)tile * SY_TILE_BYTES,
            SY_TILE_BYTES, mbar);
    const unsigned b  = tile >> 9;                 // 512 tiles per batch plane
    const unsigned p0 = (tile << 7) & (HW4 - 1);   // first group index in plane
    #pragma unroll
    for (int c = 0; c < 3; ++c) {
        const size_t off = ((size_t)(b * 3 + c) * HW4 + p0) * 16;  // bytes
        bulk_cp(smem_u32(st->t[c]), (const char*)tg + off, CH_TILE_BYTES, mbar);
        bulk_cp(smem_u32(st->m[c]), (const char*)mu + off, CH_TILE_BYTES, mbar);
    }
}

__global__ __launch_bounds__(TPB) void map_loss_fused(
    const float* __restrict__ tg,
    const float* __restrict__ mu,
    const float* __restrict__ sy,
    float* __restrict__ out)
{
    __shared__ alignas(128) SmemStage s_stage[2];   // 2 x 30720 B
    __shared__ alignas(8)  uint64_t s_mbar[2];

    const unsigned tid       = threadIdx.x;
    const unsigned base_tile = blockIdx.x * TILES;

    // ---- init barriers, prefetch tiles 0 and 1 ----
    if (tid == 0) {
        asm volatile("mbarrier.init.shared.b64 [%0], 1;" :: "r"(smem_u32(&s_mbar[0])) : "memory");
        asm volatile("mbarrier.init.shared.b64 [%0], 1;" :: "r"(smem_u32(&s_mbar[1])) : "memory");
    }
    __syncthreads();
    if (tid == 0) {
        tma_tile(&s_stage[0], sy, tg, mu, base_tile + 0, smem_u32(&s_mbar[0]));
        tma_tile(&s_stage[1], sy, tg, mu, base_tile + 1, smem_u32(&s_mbar[1]));
    }

    float lsum = 0.0f;
    float lmax = -3.0e38f;

    #pragma unroll
    for (int t = 0; t < TILES; ++t) {
        const int      stage  = t & 1;
        const uint32_t parity = (t >> 1) & 1;
        const SmemStage* st = &s_stage[stage];

        mbar_wait(smem_u32(&s_mbar[stage]), parity);

        // residuals from smem (conflict-free: 16B/thread consecutive)
        const float4 T0 = st->t[0][tid], M0 = st->m[0][tid];
        const float4 T1 = st->t[1][tid], M1 = st->m[1][tid];
        const float4 T2 = st->t[2][tid], M2 = st->m[2][tid];
        const float r0[4] = {T0.x - M0.x, T0.y - M0.y, T0.z - M0.z, T0.w - M0.w};
        const float r1[4] = {T1.x - M1.x, T1.y - M1.y, T1.z - M1.z, T1.w - M1.w};
        const float r2[4] = {T2.x - M2.x, T2.y - M2.y, T2.z - M2.z, T2.w - M2.w};

        float S[36];
        #pragma unroll
        for (int k = 0; k < 9; ++k) {
            const float4 v = st->sy[tid * 9 + k];
            S[4 * k + 0] = v.x; S[4 * k + 1] = v.y;
            S[4 * k + 2] = v.z; S[4 * k + 3] = v.w;
        }

        float quad[4], det[4];
        #pragma unroll
        for (int j = 0; j < 4; ++j) {
            const float a  = S[9 * j + 0];
            const float bb = S[9 * j + 1];
            const float c  = S[9 * j + 2];
            const float d  = S[9 * j + 4];
            const float e  = S[9 * j + 5];
            const float f  = S[9 * j + 8];
            const float A00 = d * f - e * e;
            const float A01 = c * e - bb * f;
            const float A02 = bb * e - c * d;
            const float A11 = a * f - c * c;
            const float A12 = bb * c - a * e;
            const float A22 = a * d - bb * bb;
            det[j] = a * A00 + bb * A01 + c * A02;
            quad[j] = r0[j] * r0[j] * A00 + r1[j] * r1[j] * A11 + r2[j] * r2[j] * A22
                    + 2.0f * (r0[j] * r1[j] * A01 + r0[j] * r2[j] * A02 + r1[j] * r2[j] * A12);
            // guard: t1 = 0.5*quad/det > 1e8  <=>  quad - 2e8*det > 0  (det > 0)
            lmax = fmaxf(lmax, quad[j] - 2.0e8f * det[j]);
        }

        // one division + one log per 4 pixels
        const float d01 = det[0] * det[1];
        const float d23 = det[2] * det[3];
        const float num = (quad[0] * det[1] + quad[1] * det[0]) * d23
                        + (quad[2] * det[3] + quad[3] * det[2]) * d01;
        const float dp  = d01 * d23;            // dets >= 1, product <= ~1e13 : safe
        lsum += 0.5f * (__fdividef(num, dp) + __logf(dp));

        // stage free -> refill with tile t+2
        if (t + 2 < TILES) {
            __syncthreads();
            if (tid == 0)
                tma_tile(&s_stage[stage], sy, tg, mu, base_tile + t + 2,
                         smem_u32(&s_mbar[stage]));
        }
    }

    // ---- intra-block reduction (4 warps) ----
    const int lane = tid & 31;
    const int wid  = tid >> 5;
    #pragma unroll
    for (int off = 16; off > 0; off >>= 1) {
        lsum += __shfl_down_sync(0xffffffffu, lsum, off);
        lmax  = fmaxf(lmax, __shfl_down_sync(0xffffffffu, lmax, off));
    }
    __shared__ float wsum[TPB / 32];
    __shared__ float wmax[TPB / 32];
    if (lane == 0) { wsum[wid] = lsum; wmax[wid] = lmax; }
    __syncthreads();
    __shared__ bool s_last;
    if (tid == 0) {
        float bs = wsum[0], bm = wmax[0];
        #pragma unroll
        for (int w = 1; w < TPB / 32; ++w) { bs += wsum[w]; bm = fmaxf(bm, wmax[w]); }
        g_psum[blockIdx.x] = bs;
        g_pmax[blockIdx.x] = bm;
        __threadfence();
        const unsigned done = atomicAdd(&g_count, 1u);
        s_last = (done == GRID - 1);
    }
    __syncthreads();

    // ---- last block finalizes (no second launch) ----
    if (s_last) {
        double ds = 0.0;
        float  dm = -3.0e38f;
        #pragma unroll
        for (int k = 0; k < GRID / TPB; ++k) {
            const int idx = tid + k * TPB;
            ds += (double)g_psum[idx];
            dm  = fmaxf(dm, g_pmax[idx]);
        }
        __shared__ double fsum[TPB];
        __shared__ float  fmaxv[TPB];
        fsum[tid]  = ds;
        fmaxv[tid] = dm;
        __syncthreads();
        #pragma unroll
        for (int off = TPB / 2; off > 0; off >>= 1) {
            if (tid < off) {
                fsum[tid] += fsum[tid + off];
                fmaxv[tid] = fmaxf(fmaxv[tid], fmaxv[tid + off]);
            }
            __syncthreads();
        }
        if (tid == 0) {
            float loss = (float)(fsum[0] / (double)NPIX);
            if (fmaxv[0] > 0.0f) loss = 0.0f;   // max(t1) > 1e8 guard
            out[0] = loss;
            g_count = 0;                         // reset for next graph replay
        }
    }
}

extern "C" void kernel_launch(void* const* d_in, const int* in_sizes, int n_in,
                              void* d_out, int out_size)
{
    // metadata order: target, mu, sigma_mu, sigma_n, sigma_y
    const float* target = (const float*)d_in[0];
    const float* mu     = (const float*)d_in[1];
    const float* sy     = (const float*)d_in[4];
    float* out = (float*)d_out;

    map_loss_fused<<<GRID, TPB>>>(target, mu, sy, out);
}

// round 7
// speedup vs baseline: 1.2630x; 1.0047x over previous
#include <cuda_runtime.h>
#include <cstdint>

// Problem constants
#define HW4     65536          // (512*512)/4 float4-groups per (b,c) plane
#define NGROUP  524288         // NPIX/4
#define NPIX    2097152
#define TPB     128
#define GPB     128            // groups per tile (== TPB, 1 group/thread)
#define NTILES  4096           // NGROUP / GPB
#define GRID    444            // 148 SMs x 3 resident blocks -> single wave

#define SY_TILE_BYTES  (GPB * 36 * 4)     // 18432 B sigma_y per tile
#define CH_TILE_BYTES  (GPB * 16)         // 2048 B per channel segment
#define TILE_TX_BYTES  (SY_TILE_BYTES + 6 * CH_TILE_BYTES)   // 30720 B

__device__ float        g_psum[GRID];
__device__ float        g_pmax[GRID];
__device__ unsigned int g_count = 0;

__device__ __forceinline__ uint32_t smem_u32(const void* p) {
    uint32_t a;
    asm("{ .reg .u64 t; cvta.to.shared.u64 t, %1; cvt.u32.u64 %0, t; }" : "=r"(a) : "l"(p));
    return a;
}

__device__ __forceinline__ void bulk_cp(uint32_t dst, const void* src,
                                        uint32_t bytes, uint32_t mbar) {
    asm volatile(
        "cp.async.bulk.shared::cta.global.mbarrier::complete_tx::bytes "
        "[%0], [%1], %2, [%3];"
        :: "r"(dst), "l"(src), "r"(bytes), "r"(mbar) : "memory");
}

__device__ __forceinline__ void mbar_wait(uint32_t mbar, uint32_t parity) {
    uint32_t done;
    asm volatile(
        "{\n\t.reg .pred p;\n\t"
        "mbarrier.try_wait.parity.acquire.cta.shared::cta.b64 p, [%1], %2;\n\t"
        "selp.b32 %0, 1, 0, p;\n\t}"
        : "=r"(done) : "r"(mbar), "r"(parity) : "memory");
    while (!done) {
        asm volatile(
            "{\n\t.reg .pred p;\n\t"
            "mbarrier.try_wait.parity.acquire.cta.shared::cta.b64 p, [%1], %2, 0x989680;\n\t"
            "selp.b32 %0, 1, 0, p;\n\t}"
            : "=r"(done) : "r"(mbar), "r"(parity) : "memory");
    }
}

struct SmemStage {
    float4 sy[GPB * 9];     // 18432 B
    float4 t[3][GPB];       //  6144 B
    float4 m[3][GPB];       //  6144 B
};

__device__ __forceinline__ void tma_tile(const SmemStage* st, const float* sy,
                                         const float* tg, const float* mu,
                                         unsigned tile, uint32_t mbar) {
    asm volatile("mbarrier.arrive.expect_tx.shared.b64 _, [%0], %1;"
                 :: "r"(mbar), "r"((uint32_t)TILE_TX_BYTES) : "memory");
    bulk_cp(smem_u32(st->sy), (const char*)sy + (size_t)tile * SY_TILE_BYTES,
            SY_TILE_BYTES, mbar);
    const unsigned b  = tile >> 9;                 // 512 tiles per batch plane
    const unsigned p0 = (tile << 7) & (HW4 - 1);   // first group index in plane
    #pragma unroll
    for (int c = 0; c < 3; ++c) {
        const size_t off = ((size_t)(b * 3 + c) * HW4 + p0) * 16;  // bytes
        bulk_cp(smem_u32(st->t[c]), (const char*)tg + off, CH_TILE_BYTES, mbar);
        bulk_cp(smem_u32(st->m[c]), (const char*)mu + off, CH_TILE_BYTES, mbar);
    }
}

__global__ __launch_bounds__(TPB) void map_loss_fused(
    const float* __restrict__ tg,
    const float* __restrict__ mu,
    const float* __restrict__ sy,
    float* __restrict__ out)
{
    __shared__ alignas(128) SmemStage s_stage[2];   // 2 x 30720 B
    __shared__ alignas(8)  uint64_t s_mbar[2];

    const unsigned tid = threadIdx.x;
    const unsigned bid = blockIdx.x;
    // strided tile assignment: bid, bid+GRID, bid+2*GRID, ...
    const int ntile = (NTILES - (int)bid + GRID - 1) / GRID;   // 9 or 10

    // ---- init barriers, prefetch tiles 0 and 1 of this block ----
    if (tid == 0) {
        asm volatile("mbarrier.init.shared.b64 [%0], 1;" :: "r"(smem_u32(&s_mbar[0])) : "memory");
        asm volatile("mbarrier.init.shared.b64 [%0], 1;" :: "r"(smem_u32(&s_mbar[1])) : "memory");
    }
    __syncthreads();
    if (tid == 0) {
        tma_tile(&s_stage[0], sy, tg, mu, bid, smem_u32(&s_mbar[0]));
        if (ntile > 1)
            tma_tile(&s_stage[1], sy, tg, mu, bid + GRID, smem_u32(&s_mbar[1]));
    }

    float lsum = 0.0f;
    float lmax = -3.0e38f;

    for (int k = 0; k < ntile; ++k) {
        const int      stage  = k & 1;
        const uint32_t parity = (k >> 1) & 1;
        const SmemStage* st = &s_stage[stage];

        mbar_wait(smem_u32(&s_mbar[stage]), parity);

        // residuals from smem (conflict-free: 16B/thread consecutive)
        const float4 T0 = st->t[0][tid], M0 = st->m[0][tid];
        const float4 T1 = st->t[1][tid], M1 = st->m[1][tid];
        const float4 T2 = st->t[2][tid], M2 = st->m[2][tid];
        const float r0[4] = {T0.x - M0.x, T0.y - M0.y, T0.z - M0.z, T0.w - M0.w};
        const float r1[4] = {T1.x - M1.x, T1.y - M1.y, T1.z - M1.z, T1.w - M1.w};
        const float r2[4] = {T2.x - M2.x, T2.y - M2.y, T2.z - M2.z, T2.w - M2.w};

        float S[36];
        #pragma unroll
        for (int q = 0; q < 9; ++q) {
            const float4 v = st->sy[tid * 9 + q];
            S[4 * q + 0] = v.x; S[4 * q + 1] = v.y;
            S[4 * q + 2] = v.z; S[4 * q + 3] = v.w;
        }

        float quad[4], det[4];
        #pragma unroll
        for (int j = 0; j < 4; ++j) {
            const float a  = S[9 * j + 0];
            const float bb = S[9 * j + 1];
            const float c  = S[9 * j + 2];
            const float d  = S[9 * j + 4];
            const float e  = S[9 * j + 5];
            const float f  = S[9 * j + 8];
            const float A00 = d * f - e * e;
            const float A01 = c * e - bb * f;
            const float A02 = bb * e - c * d;
            const float A11 = a * f - c * c;
            const float A12 = bb * c - a * e;
            const float A22 = a * d - bb * bb;
            det[j] = a * A00 + bb * A01 + c * A02;
            quad[j] = r0[j] * r0[j] * A00 + r1[j] * r1[j] * A11 + r2[j] * r2[j] * A22
                    + 2.0f * (r0[j] * r1[j] * A01 + r0[j] * r2[j] * A02 + r1[j] * r2[j] * A12);
            // guard: t1 = 0.5*quad/det > 1e8  <=>  quad - 2e8*det > 0  (det > 0)
            lmax = fmaxf(lmax, quad[j] - 2.0e8f * det[j]);
        }

        // one division + one log per 4 pixels
        const float d01 = det[0] * det[1];
        const float d23 = det[2] * det[3];
        const float num = (quad[0] * det[1] + quad[1] * det[0]) * d23
                        + (quad[2] * det[3] + quad[3] * det[2]) * d01;
        const float dp  = d01 * d23;            // dets >= 1, product <= ~1e13 : safe
        lsum += 0.5f * (__fdividef(num, dp) + __logf(dp));

        // stage free -> refill with tile k+2
        if (k + 2 < ntile) {
            __syncthreads();
            if (tid == 0)
                tma_tile(&s_stage[stage], sy, tg, mu, bid + (unsigned)(k + 2) * GRID,
                         smem_u32(&s_mbar[stage]));
        }
    }

    // ---- intra-block reduction (4 warps) ----
    const int lane = tid & 31;
    const int wid  = tid >> 5;
    #pragma unroll
    for (int off = 16; off > 0; off >>= 1) {
        lsum += __shfl_down_sync(0xffffffffu, lsum, off);
        lmax  = fmaxf(lmax, __shfl_down_sync(0xffffffffu, lmax, off));
    }
    __shared__ float wsum[TPB / 32];
    __shared__ float wmax[TPB / 32];
    if (lane == 0) { wsum[wid] = lsum; wmax[wid] = lmax; }
    __syncthreads();
    __shared__ bool s_last;
    if (tid == 0) {
        float bs = wsum[0], bm = wmax[0];
        #pragma unroll
        for (int w = 1; w < TPB / 32; ++w) { bs += wsum[w]; bm = fmaxf(bm, wmax[w]); }
        g_psum[bid] = bs;
        g_pmax[bid] = bm;
        __threadfence();
        const unsigned done = atomicAdd(&g_count, 1u);
        s_last = (done == GRID - 1);
    }
    __syncthreads();

    // ---- last block finalizes (no second launch) ----
    if (s_last) {
        double ds = 0.0;
        float  dm = -3.0e38f;
        #pragma unroll
        for (int k = 0; k < (GRID + TPB - 1) / TPB; ++k) {
            const int idx = tid + k * TPB;
            if (idx < GRID) {
                ds += (double)g_psum[idx];
                dm  = fmaxf(dm, g_pmax[idx]);
            }
        }
        __shared__ double fsum[TPB];
        __shared__ float  fmaxv[TPB];
        fsum[tid]  = ds;
        fmaxv[tid] = dm;
        __syncthreads();
        #pragma unroll
        for (int off = TPB / 2; off > 0; off >>= 1) {
            if (tid < off) {
                fsum[tid] += fsum[tid + off];
                fmaxv[tid] = fmaxf(fmaxv[tid], fmaxv[tid + off]);
            }
            __syncthreads();
        }
        if (tid == 0) {
            float loss = (float)(fsum[0] / (double)NPIX);
            if (fmaxv[0] > 0.0f) loss = 0.0f;   // max(t1) > 1e8 guard
            out[0] = loss;
            g_count = 0;                         // reset for next graph replay
        }
    }
}

extern "C" void kernel_launch(void* const* d_in, const int* in_sizes, int n_in,
                              void* d_out, int out_size)
{
    // metadata order: target, mu, sigma_mu, sigma_n, sigma_y
    const float* target = (const float*)d_in[0];
    const float* mu     = (const float*)d_in[1];
    const float* sy     = (const float*)d_in[4];
    float* out = (float*)d_out;

    map_loss_fused<<<GRID, TPB>>>(target, mu, sy, out);
}

// round 8
// speedup vs baseline: 1.2782x; 1.0120x over previous
#include <cuda_runtime.h>
#include <cstdint>

// Problem constants
#define HW4     65536          // (512*512)/4 float4-groups per (b,c) plane
#define NGROUP  524288         // NPIX/4
#define NPIX    2097152
#define TPB     128
#define GPB     128            // groups per tile (== TPB, 1 group/thread)
#define NTILES  4096           // NGROUP / GPB
#define GRID    296            // 148 SMs x 2 resident blocks (92KB smem each)
#define STAGES  3

#define SY_TILE_BYTES  (GPB * 36 * 4)     // 18432 B sigma_y per tile
#define CH_TILE_BYTES  (GPB * 16)         // 2048 B per channel segment
#define TILE_TX_BYTES  (SY_TILE_BYTES + 6 * CH_TILE_BYTES)   // 30720 B

__device__ float        g_psum[GRID];
__device__ float        g_pmax[GRID];
__device__ unsigned int g_count = 0;

__device__ __forceinline__ uint32_t smem_u32(const void* p) {
    uint32_t a;
    asm("{ .reg .u64 t; cvta.to.shared.u64 t, %1; cvt.u32.u64 %0, t; }" : "=r"(a) : "l"(p));
    return a;
}

__device__ __forceinline__ void bulk_cp(uint32_t dst, const void* src,
                                        uint32_t bytes, uint32_t mbar) {
    asm volatile(
        "cp.async.bulk.shared::cta.global.mbarrier::complete_tx::bytes "
        "[%0], [%1], %2, [%3];"
        :: "r"(dst), "l"(src), "r"(bytes), "r"(mbar) : "memory");
}

__device__ __forceinline__ void mbar_wait(uint32_t mbar, uint32_t parity) {
    uint32_t done;
    asm volatile(
        "{\n\t.reg .pred p;\n\t"
        "mbarrier.try_wait.parity.acquire.cta.shared::cta.b64 p, [%1], %2;\n\t"
        "selp.b32 %0, 1, 0, p;\n\t}"
        : "=r"(done) : "r"(mbar), "r"(parity) : "memory");
    while (!done) {
        asm volatile(
            "{\n\t.reg .pred p;\n\t"
            "mbarrier.try_wait.parity.acquire.cta.shared::cta.b64 p, [%1], %2, 0x989680;\n\t"
            "selp.b32 %0, 1, 0, p;\n\t}"
            : "=r"(done) : "r"(mbar), "r"(parity) : "memory");
    }
}

struct SmemStage {
    float4 sy[GPB * 9];     // 18432 B
    float4 t[3][GPB];       //  6144 B
    float4 m[3][GPB];       //  6144 B
};

__device__ __forceinline__ void tma_tile(const SmemStage* st, const float* sy,
                                         const float* tg, const float* mu,
                                         unsigned tile, uint32_t mbar) {
    asm volatile("mbarrier.arrive.expect_tx.shared.b64 _, [%0], %1;"
                 :: "r"(mbar), "r"((uint32_t)TILE_TX_BYTES) : "memory");
    bulk_cp(smem_u32(st->sy), (const char*)sy + (size_t)tile * SY_TILE_BYTES,
            SY_TILE_BYTES, mbar);
    const unsigned b  = tile >> 9;                 // 512 tiles per batch plane
    const unsigned p0 = (tile << 7) & (HW4 - 1);   // first group index in plane
    #pragma unroll
    for (int c = 0; c < 3; ++c) {
        const size_t off = ((size_t)(b * 3 + c) * HW4 + p0) * 16;  // bytes
        bulk_cp(smem_u32(st->t[c]), (const char*)tg + off, CH_TILE_BYTES, mbar);
        bulk_cp(smem_u32(st->m[c]), (const char*)mu + off, CH_TILE_BYTES, mbar);
    }
}

__global__ __launch_bounds__(TPB) void map_loss_fused(
    const float* __restrict__ tg,
    const float* __restrict__ mu,
    const float* __restrict__ sy,
    float* __restrict__ out)
{
    extern __shared__ __align__(128) SmemStage s_stage[];   // STAGES x 30720 B
    __shared__ alignas(8) uint64_t s_mbar[STAGES];

    const unsigned tid = threadIdx.x;
    const unsigned bid = blockIdx.x;
    // strided tile assignment: bid, bid+GRID, bid+2*GRID, ...
    const int ntile = (NTILES - (int)bid + GRID - 1) / GRID;   // 13 or 14

    // ---- init barriers, prefetch up to STAGES tiles ----
    if (tid == 0) {
        #pragma unroll
        for (int s = 0; s < STAGES; ++s)
            asm volatile("mbarrier.init.shared.b64 [%0], 1;"
                         :: "r"(smem_u32(&s_mbar[s])) : "memory");
    }
    __syncthreads();
    if (tid == 0) {
        #pragma unroll
        for (int s = 0; s < STAGES; ++s)
            if (s < ntile)
                tma_tile(&s_stage[s], sy, tg, mu, bid + (unsigned)s * GRID,
                         smem_u32(&s_mbar[s]));
    }

    float lsum = 0.0f;
    float lmax = -3.0e38f;

    int stage = 0, parity = 0;
    for (int k = 0; k < ntile; ++k) {
        const SmemStage* st = &s_stage[stage];

        mbar_wait(smem_u32(&s_mbar[stage]), (uint32_t)parity);

        // pull everything into registers (conflict-free LDS.128 patterns)
        const float4 T0 = st->t[0][tid], M0 = st->m[0][tid];
        const float4 T1 = st->t[1][tid], M1 = st->m[1][tid];
        const float4 T2 = st->t[2][tid], M2 = st->m[2][tid];
        float S[36];
        #pragma unroll
        for (int q = 0; q < 9; ++q) {
            const float4 v = st->sy[tid * 9 + q];
            S[4 * q + 0] = v.x; S[4 * q + 1] = v.y;
            S[4 * q + 2] = v.z; S[4 * q + 3] = v.w;
        }

        // ---- EARLY RE-ARM: buffer consumed, refill before doing the math ----
        __syncthreads();
        if (tid == 0 && k + STAGES < ntile)
            tma_tile(st, sy, tg, mu, bid + (unsigned)(k + STAGES) * GRID,
                     smem_u32(&s_mbar[stage]));

        // advance ring cursor
        if (++stage == STAGES) { stage = 0; parity ^= 1; }

        // ---- math (fully off the producer critical path) ----
        const float r0[4] = {T0.x - M0.x, T0.y - M0.y, T0.z - M0.z, T0.w - M0.w};
        const float r1[4] = {T1.x - M1.x, T1.y - M1.y, T1.z - M1.z, T1.w - M1.w};
        const float r2[4] = {T2.x - M2.x, T2.y - M2.y, T2.z - M2.z, T2.w - M2.w};

        float quad[4], det[4];
        #pragma unroll
        for (int j = 0; j < 4; ++j) {
            const float a  = S[9 * j + 0];
            const float bb = S[9 * j + 1];
            const float c  = S[9 * j + 2];
            const float d  = S[9 * j + 4];
            const float e  = S[9 * j + 5];
            const float f  = S[9 * j + 8];
            const float A00 = d * f - e * e;
            const float A01 = c * e - bb * f;
            const float A02 = bb * e - c * d;
            const float A11 = a * f - c * c;
            const float A12 = bb * c - a * e;
            const float A22 = a * d - bb * bb;
            det[j] = a * A00 + bb * A01 + c * A02;
            quad[j] = r0[j] * r0[j] * A00 + r1[j] * r1[j] * A11 + r2[j] * r2[j] * A22
                    + 2.0f * (r0[j] * r1[j] * A01 + r0[j] * r2[j] * A02 + r1[j] * r2[j] * A12);
            // guard: t1 = 0.5*quad/det > 1e8  <=>  quad - 2e8*det > 0  (det > 0)
            lmax = fmaxf(lmax, quad[j] - 2.0e8f * det[j]);
        }

        // one division + one log per 4 pixels
        const float d01 = det[0] * det[1];
        const float d23 = det[2] * det[3];
        const float num = (quad[0] * det[1] + quad[1] * det[0]) * d23
                        + (quad[2] * det[3] + quad[3] * det[2]) * d01;
        const float dp  = d01 * d23;            // dets >= 1, product <= ~1e13 : safe
        lsum += 0.5f * (__fdividef(num, dp) + __logf(dp));
    }

    // ---- intra-block reduction (4 warps) ----
    const int lane = tid & 31;
    const int wid  = tid >> 5;
    #pragma unroll
    for (int off = 16; off > 0; off >>= 1) {
        lsum += __shfl_down_sync(0xffffffffu, lsum, off);
        lmax  = fmaxf(lmax, __shfl_down_sync(0xffffffffu, lmax, off));
    }
    __shared__ float wsum[TPB / 32];
    __shared__ float wmax[TPB / 32];
    if (lane == 0) { wsum[wid] = lsum; wmax[wid] = lmax; }
    __syncthreads();
    __shared__ bool s_last;
    if (tid == 0) {
        float bs = wsum[0], bm = wmax[0];
        #pragma unroll
        for (int w = 1; w < TPB / 32; ++w) { bs += wsum[w]; bm = fmaxf(bm, wmax[w]); }
        g_psum[bid] = bs;
        g_pmax[bid] = bm;
        __threadfence();
        const unsigned done = atomicAdd(&g_count, 1u);
        s_last = (done == GRID - 1);
    }
    __syncthreads();

    // ---- last block finalizes (no second launch) ----
    if (s_last) {
        double ds = 0.0;
        float  dm = -3.0e38f;
        #pragma unroll
        for (int k = 0; k < (GRID + TPB - 1) / TPB; ++k) {
            const int idx = tid + k * TPB;
            if (idx < GRID) {
                ds += (double)g_psum[idx];
                dm  = fmaxf(dm, g_pmax[idx]);
            }
        }
        __shared__ double fsum[TPB];
        __shared__ float  fmaxv[TPB];
        fsum[tid]  = ds;
        fmaxv[tid] = dm;
        __syncthreads();
        #pragma unroll
        for (int off = TPB / 2; off > 0; off >>= 1) {
            if (tid < off) {
                fsum[tid] += fsum[tid + off];
                fmaxv[tid] = fmaxf(fmaxv[tid], fmaxv[tid + off]);
            }
            __syncthreads();
        }
        if (tid == 0) {
            float loss = (float)(fsum[0] / (double)NPIX);
            if (fmaxv[0] > 0.0f) loss = 0.0f;   // max(t1) > 1e8 guard
            out[0] = loss;
            g_count = 0;                         // reset for next graph replay
        }
    }
}

extern "C" void kernel_launch(void* const* d_in, const int* in_sizes, int n_in,
                              void* d_out, int out_size)
{
    // metadata order: target, mu, sigma_mu, sigma_n, sigma_y
    const float* target = (const float*)d_in[0];
    const float* mu     = (const float*)d_in[1];
    const float* sy     = (const float*)d_in[4];
    float* out = (float*)d_out;

    const int smem_bytes = STAGES * (int)sizeof(SmemStage);   // 92160 B
    cudaFuncSetAttribute(map_loss_fused,
                         cudaFuncAttributeMaxDynamicSharedMemorySize, smem_bytes);
    map_loss_fused<<<GRID, TPB, smem_bytes>>>(target, mu, sy, out);
}

// round 9
// speedup vs baseline: 1.3597x; 1.0638x over previous
#include <cuda_runtime.h>
#include <cstdint>

// Problem constants
#define HW4     65536          // (512*512)/4 float4-groups per (b,c) plane
#define NGROUP  524288         // NPIX/4
#define NPIX    2097152
#define TPB     128
#define GPB     128            // groups per tile (== TPB, 1 group/thread)
#define NTILES  4096           // NGROUP / GPB
#define GRID    592            // 148 SMs x 4 resident blocks
#define STAGES  2

#define SY_TILE_BYTES  (GPB * 36 * 4)     // 18432 B sigma_y per tile

__device__ float        g_psum[GRID];
__device__ float        g_pmax[GRID];
__device__ unsigned int g_count = 0;

__device__ __forceinline__ uint32_t smem_u32(const void* p) {
    uint32_t a;
    asm("{ .reg .u64 t; cvta.to.shared.u64 t, %1; cvt.u32.u64 %0, t; }" : "=r"(a) : "l"(p));
    return a;
}

__device__ __forceinline__ void tma_sigma(const float4* dst, const float* sy,
                                          unsigned tile, uint32_t mbar) {
    asm volatile("mbarrier.arrive.expect_tx.shared.b64 _, [%0], %1;"
                 :: "r"(mbar), "r"((uint32_t)SY_TILE_BYTES) : "memory");
    asm volatile(
        "cp.async.bulk.shared::cta.global.mbarrier::complete_tx::bytes "
        "[%0], [%1], %2, [%3];"
        :: "r"(smem_u32(dst)),
           "l"((const char*)sy + (size_t)tile * SY_TILE_BYTES),
           "r"((uint32_t)SY_TILE_BYTES), "r"(mbar) : "memory");
}

__device__ __forceinline__ void mbar_wait(uint32_t mbar, uint32_t parity) {
    uint32_t done;
    asm volatile(
        "{\n\t.reg .pred p;\n\t"
        "mbarrier.try_wait.parity.acquire.cta.shared::cta.b64 p, [%1], %2;\n\t"
        "selp.b32 %0, 1, 0, p;\n\t}"
        : "=r"(done) : "r"(mbar), "r"(parity) : "memory");
    while (!done) {
        asm volatile(
            "{\n\t.reg .pred p;\n\t"
            "mbarrier.try_wait.parity.acquire.cta.shared::cta.b64 p, [%1], %2, 0x989680;\n\t"
            "selp.b32 %0, 1, 0, p;\n\t}"
            : "=r"(done) : "r"(mbar), "r"(parity) : "memory");
    }
}

// load the 6 tg/mu float4s for a tile (issued early = software prefetch)
__device__ __forceinline__ void load_tm(const float4* __restrict__ tg,
                                        const float4* __restrict__ mu,
                                        unsigned tile, unsigned tid,
                                        float4& T0, float4& T1, float4& T2,
                                        float4& M0, float4& M1, float4& M2) {
    const unsigned g  = tile * GPB + tid;
    const unsigned b  = g >> 16;
    const unsigned p  = g & (HW4 - 1);
    const unsigned tb = b * 3 * HW4 + p;
    T0 = tg[tb];           M0 = mu[tb];
    T1 = tg[tb + HW4];     M1 = mu[tb + HW4];
    T2 = tg[tb + 2 * HW4]; M2 = mu[tb + 2 * HW4];
}

__global__ __launch_bounds__(TPB, 4) void map_loss_fused(
    const float4* __restrict__ tg,
    const float4* __restrict__ mu,
    const float*  __restrict__ sy,
    float* __restrict__ out)
{
    __shared__ alignas(128) float4 s_sy[STAGES][GPB * 9];   // 2 x 18432 B
    __shared__ alignas(8)  uint64_t s_mbar[STAGES];

    const unsigned tid = threadIdx.x;
    const unsigned bid = blockIdx.x;
    const int ntile = (NTILES - (int)bid + GRID - 1) / GRID;   // 6 or 7

    if (tid == 0) {
        asm volatile("mbarrier.init.shared.b64 [%0], 1;" :: "r"(smem_u32(&s_mbar[0])) : "memory");
        asm volatile("mbarrier.init.shared.b64 [%0], 1;" :: "r"(smem_u32(&s_mbar[1])) : "memory");
    }
    __syncthreads();
    if (tid == 0) {
        tma_sigma(s_sy[0], sy, bid, smem_u32(&s_mbar[0]));
        if (ntile > 1)
            tma_sigma(s_sy[1], sy, bid + GRID, smem_u32(&s_mbar[1]));
    }

    // register prefetch of tg/mu for tile 0
    float4 cT0, cT1, cT2, cM0, cM1, cM2;
    load_tm(tg, mu, bid, tid, cT0, cT1, cT2, cM0, cM1, cM2);

    float lsum = 0.0f;
    float lmax = -3.0e38f;

    for (int k = 0; k < ntile; ++k) {
        const int      stage  = k & 1;
        const uint32_t parity = (k >> 1) & 1;

        // prefetch tg/mu for NEXT tile before blocking on this tile's sigma
        float4 nT0, nT1, nT2, nM0, nM1, nM2;
        if (k + 1 < ntile)
            load_tm(tg, mu, bid + (unsigned)(k + 1) * GRID, tid,
                    nT0, nT1, nT2, nM0, nM1, nM2);

        mbar_wait(smem_u32(&s_mbar[stage]), parity);

        // sigma -> registers, then free the buffer immediately
        float S[36];
        #pragma unroll
        for (int q = 0; q < 9; ++q) {
            const float4 v = s_sy[stage][tid * 9 + q];
            S[4 * q + 0] = v.x; S[4 * q + 1] = v.y;
            S[4 * q + 2] = v.z; S[4 * q + 3] = v.w;
        }
        __syncthreads();
        if (tid == 0 && k + STAGES < ntile)
            tma_sigma(s_sy[stage], sy, bid + (unsigned)(k + STAGES) * GRID,
                      smem_u32(&s_mbar[stage]));

        // ---- math ----
        const float r0[4] = {cT0.x - cM0.x, cT0.y - cM0.y, cT0.z - cM0.z, cT0.w - cM0.w};
        const float r1[4] = {cT1.x - cM1.x, cT1.y - cM1.y, cT1.z - cM1.z, cT1.w - cM1.w};
        const float r2[4] = {cT2.x - cM2.x, cT2.y - cM2.y, cT2.z - cM2.z, cT2.w - cM2.w};

        float quad[4], det[4];
        #pragma unroll
        for (int j = 0; j < 4; ++j) {
            const float a  = S[9 * j + 0];
            const float bb = S[9 * j + 1];
            const float c  = S[9 * j + 2];
            const float d  = S[9 * j + 4];
            const float e  = S[9 * j + 5];
            const float f  = S[9 * j + 8];
            const float A00 = d * f - e * e;
            const float A01 = c * e - bb * f;
            const float A02 = bb * e - c * d;
            const float A11 = a * f - c * c;
            const float A12 = bb * c - a * e;
            const float A22 = a * d - bb * bb;
            det[j] = a * A00 + bb * A01 + c * A02;
            quad[j] = r0[j] * r0[j] * A00 + r1[j] * r1[j] * A11 + r2[j] * r2[j] * A22
                    + 2.0f * (r0[j] * r1[j] * A01 + r0[j] * r2[j] * A02 + r1[j] * r2[j] * A12);
            // guard: t1 = 0.5*quad/det > 1e8  <=>  quad - 2e8*det > 0  (det > 0)
            lmax = fmaxf(lmax, quad[j] - 2.0e8f * det[j]);
        }

        const float d01 = det[0] * det[1];
        const float d23 = det[2] * det[3];
        const float num = (quad[0] * det[1] + quad[1] * det[0]) * d23
                        + (quad[2] * det[3] + quad[3] * det[2]) * d01;
        const float dp  = d01 * d23;            // dets >= 1, product <= ~1e13 : safe
        lsum += 0.5f * (__fdividef(num, dp) + __logf(dp));

        // rotate prefetched registers
        cT0 = nT0; cT1 = nT1; cT2 = nT2;
        cM0 = nM0; cM1 = nM1; cM2 = nM2;
    }

    // ---- intra-block reduction (4 warps) ----
    const int lane = tid & 31;
    const int wid  = tid >> 5;
    #pragma unroll
    for (int off = 16; off > 0; off >>= 1) {
        lsum += __shfl_down_sync(0xffffffffu, lsum, off);
        lmax  = fmaxf(lmax, __shfl_down_sync(0xffffffffu, lmax, off));
    }
    __shared__ float wsum[TPB / 32];
    __shared__ float wmax[TPB / 32];
    if (lane == 0) { wsum[wid] = lsum; wmax[wid] = lmax; }
    __syncthreads();
    __shared__ bool s_last;
    if (tid == 0) {
        float bs = wsum[0], bm = wmax[0];
        #pragma unroll
        for (int w = 1; w < TPB / 32; ++w) { bs += wsum[w]; bm = fmaxf(bm, wmax[w]); }
        g_psum[bid] = bs;
        g_pmax[bid] = bm;
        __threadfence();
        const unsigned done = atomicAdd(&g_count, 1u);
        s_last = (done == GRID - 1);
    }
    __syncthreads();

    // ---- last block finalizes (no second launch) ----
    if (s_last) {
        double ds = 0.0;
        float  dm = -3.0e38f;
        #pragma unroll
        for (int k = 0; k < (GRID + TPB - 1) / TPB; ++k) {
            const int idx = tid + k * TPB;
            if (idx < GRID) {
                ds += (double)g_psum[idx];
                dm  = fmaxf(dm, g_pmax[idx]);
            }
        }
        __shared__ double fsum[TPB];
        __shared__ float  fmaxv[TPB];
        fsum[tid]  = ds;
        fmaxv[tid] = dm;
        __syncthreads();
        #pragma unroll
        for (int off = TPB / 2; off > 0; off >>= 1) {
            if (tid < off) {
                fsum[tid] += fsum[tid + off];
                fmaxv[tid] = fmaxf(fmaxv[tid], fmaxv[tid + off]);
            }
            __syncthreads();
        }
        if (tid == 0) {
            float loss = (float)(fsum[0] / (double)NPIX);
            if (fmaxv[0] > 0.0f) loss = 0.0f;   // max(t1) > 1e8 guard
            out[0] = loss;
            g_count = 0;                         // reset for next graph replay
        }
    }
}

extern "C" void kernel_launch(void* const* d_in, const int* in_sizes, int n_in,
                              void* d_out, int out_size)
{
    // metadata order: target, mu, sigma_mu, sigma_n, sigma_y
    const float4* target = (const float4*)d_in[0];
    const float4* mu     = (const float4*)d_in[1];
    const float*  sy     = (const float*)d_in[4];
    float* out = (float*)d_out;

    map_loss_fused<<<GRID, TPB>>>(target, mu, sy, out);
}